// round 13
// baseline (speedup 1.0000x reference)
#include <cuda_runtime.h>
#include <cuda_fp16.h>
#include <math.h>

// TemporalAttentionEncoder — 2 launches.
//   kPre     : per-block (8 batches): stream x -> e_p fp16 (global) + e_mean (smem);
//              q chain -> r (smem); warp-per-batch scores + softmax -> probs.
//              b_k cancels in softmax.
//   kAttnMLP : block owns sources 8bi..8bi+7 -> 8 consumers complete (all heads).
//              Attn phase barrier-free: warp = (q, k-pair, h-pair), thread owns a
//              dim chunk and the FULL s-sum (no cross-thread reduce). MLP fused.

#define B_   4096
#define S_   64
#define D_   128
#define H_   4

__device__ __align__(16) __half g_ep16[(size_t)B_ * S_ * D_];   // 64 MB
__device__ __align__(16) float  g_probs[(size_t)B_ * H_ * S_];  // 4 MB

// ---------------------------------------------------------------------------
// Fused mean/ep + chain + scores + softmax.  8 batches/block, 256 threads.
__global__ void __launch_bounds__(256) kPre(
    const float* __restrict__ x,
    const float* __restrict__ w_q, const float* __restrict__ b_q,
    const float* __restrict__ w2,  const float* __restrict__ b2,
    const float* __restrict__ w_k)
{
    __shared__ float chainbuf[3 * 1024];             // em | qm | qh ; aliased below
    __shared__ __align__(16) float rs[8 * H_ * D_];  // 16 KB: rs[(k*4+h)*128+d]
    float* em = chainbuf;                            // 1024 floats  (8 x 128 e_mean)
    float* qm = chainbuf + 1024;
    float* qh = chainbuf + 2048;
    float4* red = (float4*)(chainbuf + 1024);        // phase-A reduce buf (aliases qm)
    float* sc = chainbuf;                            // scores buf (aliases em/qm later)

    const int t = threadIdx.x;
    const int b0 = blockIdx.x * 8;
    const int c = t & 31, r0 = t >> 5;
    const int d = t & 127, g = t >> 7;

    // pe for this thread's (rows r0+8j, dims 4c..4c+3), computed once
    float4 pe4[8];
    {
        const float f0 = __powf(1000.0f, -(float)(2 * c) / 64.0f);
        const float f1 = __powf(1000.0f, -(float)(2 * c + 1) / 64.0f);
        #pragma unroll
        for (int j = 0; j < 8; j++) {
            float row = (float)(r0 + 8 * j);
            pe4[j] = make_float4(__sinf(row * f0), __cosf(row * f0),
                                 __sinf(row * f1), __cosf(row * f1));
        }
    }

    // ---- phase A: per batch m: e_p -> fp16 global; e_mean -> em smem ----
    #pragma unroll 1
    for (int m = 0; m < 8; m++) {
        const int b = b0 + m;
        const float4* xb = (const float4*)(x + (size_t)b * (S_ * D_));
        float4 acc = make_float4(0.f, 0.f, 0.f, 0.f);
        #pragma unroll
        for (int j = 0; j < 8; j++) {
            int row = r0 + 8 * j;
            float4 v = xb[row * 32 + c];
            v.x += pe4[j].x; v.y += pe4[j].y; v.z += pe4[j].z; v.w += pe4[j].w;
            acc.x += v.x; acc.y += v.y; acc.z += v.z; acc.w += v.w;
            __half2 h0 = __floats2half2_rn(v.x, v.y);
            __half2 h1 = __floats2half2_rn(v.z, v.w);
            uint2 u;
            u.x = *(unsigned int*)&h0;
            u.y = *(unsigned int*)&h1;
            *(uint2*)&g_ep16[((size_t)b * S_ + row) * D_ + 4 * c] = u;
        }
        red[r0 * 32 + c] = acc;
        __syncthreads();
        if (t < 32) {
            float4 s = red[t];
            #pragma unroll
            for (int r = 1; r < 8; r++) {
                float4 u = red[r * 32 + t];
                s.x += u.x; s.y += u.y; s.z += u.z; s.w += u.w;
            }
            const float inv = 1.0f / (float)S_;
            *(float4*)&em[m * D_ + 4 * t] =
                make_float4(s.x * inv, s.y * inv, s.z * inv, s.w * inv);
        }
        __syncthreads();
    }

    // ---- phase B: chain (block-cooperative over 8 batches) ----
    {
        float acc[4] = {0.f, 0.f, 0.f, 0.f};
        for (int j = 0; j < D_; j++) {
            float wv = w_q[j * D_ + d];
            #pragma unroll
            for (int m = 0; m < 4; m++) acc[m] += em[(g * 4 + m) * D_ + j] * wv;
        }
        float bq = b_q[d];
        __syncthreads();   // em reads done before qm (aliases red history) written
        #pragma unroll
        for (int m = 0; m < 4; m++) qm[(g * 4 + m) * D_ + d] = acc[m] + bq;
    }
    __syncthreads();
    {
        float acc[4] = {0.f, 0.f, 0.f, 0.f};
        for (int j = 0; j < D_; j++) {
            float wv = w2[j * D_ + d];
            #pragma unroll
            for (int m = 0; m < 4; m++) acc[m] += qm[(g * 4 + m) * D_ + j] * wv;
        }
        float bb = b2[d];
        #pragma unroll
        for (int m = 0; m < 4; m++) qh[(g * 4 + m) * D_ + d] = acc[m] + bb;
    }
    __syncthreads();
    // r[k,h,d] = sum_j w_k[d][h*32+j] * qh[k][h*32+j]  (w_k row d: L1-resident)
    #pragma unroll
    for (int h = 0; h < H_; h++) {
        float acc[4] = {0.f, 0.f, 0.f, 0.f};
        #pragma unroll
        for (int j4 = 0; j4 < 8; j4++) {
            float4 wv = *(const float4*)&w_k[d * D_ + h * 32 + j4 * 4];
            #pragma unroll
            for (int m = 0; m < 4; m++) {
                float4 qv = *(const float4*)&qh[(g * 4 + m) * D_ + h * 32 + j4 * 4];
                acc[m] += wv.x * qv.x + wv.y * qv.y + wv.z * qv.z + wv.w * qv.w;
            }
        }
        #pragma unroll
        for (int m = 0; m < 4; m++) rs[((g * 4 + m) * 4 + h) * D_ + d] = acc[m];
    }
    __syncthreads();   // rs ready; em/qm dead -> sc alias safe

    // ---- phase C: scores (warp-autonomous, batch = b0 + w) ----
    const int w = t >> 5, lane = t & 31;
    const int rg = lane >> 3, u = lane & 7;
    const __half* epg = g_ep16 + (size_t)(b0 + w) * (S_ * D_);
    const float scale = 0.17677669529663689f;  // 1/sqrt(32)

    #pragma unroll 4
    for (int iter = 0; iter < 16; iter++) {
        const int s = iter * 4 + rg;
        const __half* ebase = epg + s * D_ + u * 4;
        float acc[4] = {0.f, 0.f, 0.f, 0.f};
        #pragma unroll
        for (int k = 0; k < 4; k++) {
            uint2 uu = *(const uint2*)(ebase + 32 * k);
            __half2* hp = (__half2*)&uu;
            float2 f0 = __half22float2(hp[0]);
            float2 f1 = __half22float2(hp[1]);
            #pragma unroll
            for (int h = 0; h < 4; h++) {
                float4 rv = *(const float4*)&rs[(w * 4 + h) * D_ + u * 4 + 32 * k];
                acc[h] += f0.x * rv.x + f0.y * rv.y + f1.x * rv.z + f1.y * rv.w;
            }
        }
        #pragma unroll
        for (int o = 1; o < 8; o <<= 1) {
            #pragma unroll
            for (int h = 0; h < 4; h++)
                acc[h] += __shfl_xor_sync(0xffffffffu, acc[h], o);
        }
        if (u == 0) {
            #pragma unroll
            for (int h = 0; h < 4; h++)
                sc[w * 256 + h * 64 + s] = acc[h] * scale;
        }
    }
    __syncwarp();

    // ---- phase D: softmax (warp-local), write probs ----
    #pragma unroll
    for (int h = 0; h < 4; h++) {
        float v0 = sc[w * 256 + h * 64 + lane];
        float v1 = sc[w * 256 + h * 64 + 32 + lane];
        float mx = fmaxf(v0, v1);
        #pragma unroll
        for (int o = 16; o > 0; o >>= 1) mx = fmaxf(mx, __shfl_xor_sync(0xffffffffu, mx, o));
        float e0 = expf(v0 - mx), e1 = expf(v1 - mx);
        float sum = e0 + e1;
        #pragma unroll
        for (int o = 16; o > 0; o >>= 1) sum += __shfl_xor_sync(0xffffffffu, sum, o);
        float inv = 1.0f / sum;
        float* po = g_probs + ((size_t)(b0 + w) * H_ + h) * S_;
        po[lane] = e0 * inv;
        po[32 + lane] = e1 * inv;
    }
}

// ---------------------------------------------------------------------------
// Fused attention + MLP.  Block bi owns sources 8bi..8bi+7;
// consumers b = 2bi+q + 1024k (q=0..1, k=0..3), all heads.
// Attn phase: warp w = (q = w>>2, kpair = (w>>1)&1, hpair = w&1); thread owns
// dim chunk c = lane and the FULL s-sum for 2 consumers x 2 heads (16 acc regs,
// no cross-thread reduce, no barriers). Then one sync and the MLP.
__global__ void __launch_bounds__(256) kAttnMLP(
    const float* __restrict__ w3a, const float* __restrict__ b3a,
    const float* __restrict__ g3a, const float* __restrict__ be3a,
    const float* __restrict__ w3b, const float* __restrict__ b3b,
    const float* __restrict__ g3b, const float* __restrict__ be3b,
    float* __restrict__ out)
{
    __shared__ float pr[2048];                    // 8 KB  pr[q][k][h][s]
    __shared__ __align__(16) float as[8 * 512];   // 16 KB attn rows [q*4+k][512]
    __shared__ __align__(16) float h1[8 * D_];    // 4 KB

    const int t = threadIdx.x, bi = blockIdx.x;

    // stage probs for 8 consumers x 4 heads
    #pragma unroll
    for (int z0 = 0; z0 < 8; z0++) {
        int z = t + 256 * z0;
        int q = z >> 10, k = (z >> 8) & 3, h = (z >> 6) & 3, s = z & 63;
        int b = 2 * bi + q + 1024 * k;
        pr[z] = g_probs[((size_t)b * H_ + h) * S_ + s];
    }
    __syncthreads();

    // ---- attention (barrier-free) ----
    {
        const int w = t >> 5, lane = t & 31;
        const int q = w >> 2, kp = (w >> 1) & 1, hp = w & 1;
        float4 acc[2][2];
        #pragma unroll
        for (int ki = 0; ki < 2; ki++)
            #pragma unroll
            for (int hi = 0; hi < 2; hi++)
                acc[ki][hi] = make_float4(0.f, 0.f, 0.f, 0.f);

        #pragma unroll
        for (int hi = 0; hi < 2; hi++) {
            const int h = 2 * hp + hi;
            const int j = 8 * bi + 4 * q + h;
            const __half* epg = g_ep16 + (size_t)j * (S_ * D_) + 4 * lane;
            const float* prh0 = &pr[q * 1024 + (2 * kp + 0) * 256 + h * 64];
            const float* prh1 = &pr[q * 1024 + (2 * kp + 1) * 256 + h * 64];
            #pragma unroll 8
            for (int s = 0; s < S_; s++) {
                uint2 u = *(const uint2*)(epg + s * D_);
                __half2* hpx = (__half2*)&u;
                float2 f0 = __half22float2(hpx[0]);
                float2 f1 = __half22float2(hpx[1]);
                float p0 = prh0[s];   // warp-uniform broadcast
                float p1 = prh1[s];
                acc[0][hi].x += p0 * f0.x; acc[0][hi].y += p0 * f0.y;
                acc[0][hi].z += p0 * f1.x; acc[0][hi].w += p0 * f1.y;
                acc[1][hi].x += p1 * f0.x; acc[1][hi].y += p1 * f0.y;
                acc[1][hi].z += p1 * f1.x; acc[1][hi].w += p1 * f1.y;
            }
        }
        #pragma unroll
        for (int ki = 0; ki < 2; ki++) {
            const int k = 2 * kp + ki;
            #pragma unroll
            for (int hi = 0; hi < 2; hi++) {
                const int h = 2 * hp + hi;
                *(float4*)&as[(q * 4 + k) * 512 + h * D_ + 4 * lane] = acc[ki][hi];
            }
        }
    }
    __syncthreads();

    // ---- MLP: 8 rows of as -> out. g = t>>7 owns rows g*4+m. ----
    const int d = t & 127, g = t >> 7;
    float acc[4];
    #pragma unroll
    for (int m = 0; m < 4; m++) acc[m] = 0.f;
    for (int i0 = 0; i0 < 512; i0 += 4) {
        float wv0 = w3a[(i0 + 0) * D_ + d];
        float wv1 = w3a[(i0 + 1) * D_ + d];
        float wv2 = w3a[(i0 + 2) * D_ + d];
        float wv3 = w3a[(i0 + 3) * D_ + d];
        #pragma unroll
        for (int m = 0; m < 4; m++) {
            float4 av = *(const float4*)&as[(g * 4 + m) * 512 + i0];  // broadcast
            acc[m] += av.x * wv0 + av.y * wv1 + av.z * wv2 + av.w * wv3;
        }
    }
    {
        float bb = b3a[d], gg = g3a[d], be = be3a[d];
        #pragma unroll
        for (int m = 0; m < 4; m++) {
            float v = (acc[m] + bb) * gg + be;
            h1[(g * 4 + m) * D_ + d] = fmaxf(v, 0.f);
        }
    }
    __syncthreads();

    #pragma unroll
    for (int m = 0; m < 4; m++) acc[m] = 0.f;
    for (int i0 = 0; i0 < D_; i0 += 4) {
        float wv0 = w3b[(i0 + 0) * D_ + d];
        float wv1 = w3b[(i0 + 1) * D_ + d];
        float wv2 = w3b[(i0 + 2) * D_ + d];
        float wv3 = w3b[(i0 + 3) * D_ + d];
        #pragma unroll
        for (int m = 0; m < 4; m++) {
            float4 hv = *(const float4*)&h1[(g * 4 + m) * D_ + i0];
            acc[m] += hv.x * wv0 + hv.y * wv1 + hv.z * wv2 + hv.w * wv3;
        }
    }
    {
        float bb = b3b[d], gg = g3b[d], be = be3b[d];
        #pragma unroll
        for (int m = 0; m < 4; m++) {
            float v = (acc[m] + bb) * gg + be;
            int b_out = 2 * bi + g + 1024 * m;
            out[(size_t)b_out * D_ + d] = fmaxf(v, 0.f);
        }
    }
}

// ---------------------------------------------------------------------------
extern "C" void kernel_launch(void* const* d_in, const int* in_sizes, int n_in,
                              void* d_out, int out_size) {
    const float* x    = (const float*)d_in[0];
    const float* w_q  = (const float*)d_in[1];
    const float* b_q  = (const float*)d_in[2];
    const float* w_k  = (const float*)d_in[3];
    // d_in[4] = b_k: constant over s -> cancels in softmax. Unused.
    const float* w2   = (const float*)d_in[5];
    const float* b2   = (const float*)d_in[6];
    const float* w3a  = (const float*)d_in[7];
    const float* b3a  = (const float*)d_in[8];
    const float* g3a  = (const float*)d_in[9];
    const float* be3a = (const float*)d_in[10];
    const float* w3b  = (const float*)d_in[11];
    const float* b3b  = (const float*)d_in[12];
    const float* g3b  = (const float*)d_in[13];
    const float* be3b = (const float*)d_in[14];
    float* out = (float*)d_out;

    kPre     <<<B_ / 8, 256>>>(x, w_q, b_q, w2, b2, w_k);
    kAttnMLP <<<B_ / 8, 256>>>(w3a, b3a, g3a, be3a, w3b, b3b, g3b, be3b, out);
}

// round 17
// speedup vs baseline: 1.1081x; 1.1081x over previous
#include <cuda_runtime.h>
#include <cuda_fp16.h>
#include <math.h>

// TemporalAttentionEncoder — 2 launches.
//   kPre     : per-block (8 batches): stream x -> e_p fp16 (global) + e_mean (smem);
//              q chain -> r (smem); warp-per-batch scores + softmax -> probs.
//              b_k cancels in softmax.
//   kAttnMLP : block owns sources 8bi..8bi+7. Attn: warp-per-tile (1x tile reads),
//              uint4 streaming, full-s accumulators, one shfl merge. MLP fused.

#define B_   4096
#define S_   64
#define D_   128
#define H_   4

__device__ __align__(16) __half g_ep16[(size_t)B_ * S_ * D_];   // 64 MB
__device__ __align__(16) float  g_probs[(size_t)B_ * H_ * S_];  // 4 MB

// ---------------------------------------------------------------------------
// Fused mean/ep + chain + scores + softmax.  8 batches/block, 256 threads.
__global__ void __launch_bounds__(256) kPre(
    const float* __restrict__ x,
    const float* __restrict__ w_q, const float* __restrict__ b_q,
    const float* __restrict__ w2,  const float* __restrict__ b2,
    const float* __restrict__ w_k)
{
    __shared__ float chainbuf[3 * 1024];             // em | qm | qh ; aliased below
    __shared__ __align__(16) float rs[8 * H_ * D_];  // 16 KB: rs[(k*4+h)*128+d]
    float* em = chainbuf;                            // 1024 floats  (8 x 128 e_mean)
    float* qm = chainbuf + 1024;
    float* qh = chainbuf + 2048;
    float4* red = (float4*)(chainbuf + 1024);        // phase-A reduce buf (aliases qm)
    float* sc = chainbuf;                            // scores buf (aliases em/qm later)

    const int t = threadIdx.x;
    const int b0 = blockIdx.x * 8;
    const int c = t & 31, r0 = t >> 5;
    const int d = t & 127, g = t >> 7;

    // pe for this thread's (rows r0+8j, dims 4c..4c+3), computed once
    float4 pe4[8];
    {
        const float f0 = __powf(1000.0f, -(float)(2 * c) / 64.0f);
        const float f1 = __powf(1000.0f, -(float)(2 * c + 1) / 64.0f);
        #pragma unroll
        for (int j = 0; j < 8; j++) {
            float row = (float)(r0 + 8 * j);
            pe4[j] = make_float4(__sinf(row * f0), __cosf(row * f0),
                                 __sinf(row * f1), __cosf(row * f1));
        }
    }

    // ---- phase A: per batch m: e_p -> fp16 global; e_mean -> em smem ----
    #pragma unroll 1
    for (int m = 0; m < 8; m++) {
        const int b = b0 + m;
        const float4* xb = (const float4*)(x + (size_t)b * (S_ * D_));
        float4 acc = make_float4(0.f, 0.f, 0.f, 0.f);
        #pragma unroll
        for (int j = 0; j < 8; j++) {
            int row = r0 + 8 * j;
            float4 v = xb[row * 32 + c];
            v.x += pe4[j].x; v.y += pe4[j].y; v.z += pe4[j].z; v.w += pe4[j].w;
            acc.x += v.x; acc.y += v.y; acc.z += v.z; acc.w += v.w;
            __half2 h0 = __floats2half2_rn(v.x, v.y);
            __half2 h1 = __floats2half2_rn(v.z, v.w);
            uint2 u;
            u.x = *(unsigned int*)&h0;
            u.y = *(unsigned int*)&h1;
            *(uint2*)&g_ep16[((size_t)b * S_ + row) * D_ + 4 * c] = u;
        }
        red[r0 * 32 + c] = acc;
        __syncthreads();
        if (t < 32) {
            float4 s = red[t];
            #pragma unroll
            for (int r = 1; r < 8; r++) {
                float4 u = red[r * 32 + t];
                s.x += u.x; s.y += u.y; s.z += u.z; s.w += u.w;
            }
            const float inv = 1.0f / (float)S_;
            *(float4*)&em[m * D_ + 4 * t] =
                make_float4(s.x * inv, s.y * inv, s.z * inv, s.w * inv);
        }
        __syncthreads();
    }

    // ---- phase B: chain (block-cooperative over 8 batches) ----
    {
        float acc[4] = {0.f, 0.f, 0.f, 0.f};
        for (int j = 0; j < D_; j++) {
            float wv = w_q[j * D_ + d];
            #pragma unroll
            for (int m = 0; m < 4; m++) acc[m] += em[(g * 4 + m) * D_ + j] * wv;
        }
        float bq = b_q[d];
        __syncthreads();   // em reads done before qm (aliases red history) written
        #pragma unroll
        for (int m = 0; m < 4; m++) qm[(g * 4 + m) * D_ + d] = acc[m] + bq;
    }
    __syncthreads();
    {
        float acc[4] = {0.f, 0.f, 0.f, 0.f};
        for (int j = 0; j < D_; j++) {
            float wv = w2[j * D_ + d];
            #pragma unroll
            for (int m = 0; m < 4; m++) acc[m] += qm[(g * 4 + m) * D_ + j] * wv;
        }
        float bb = b2[d];
        #pragma unroll
        for (int m = 0; m < 4; m++) qh[(g * 4 + m) * D_ + d] = acc[m] + bb;
    }
    __syncthreads();
    // r[k,h,d] = sum_j w_k[d][h*32+j] * qh[k][h*32+j]  (w_k row d: L1-resident)
    #pragma unroll
    for (int h = 0; h < H_; h++) {
        float acc[4] = {0.f, 0.f, 0.f, 0.f};
        #pragma unroll
        for (int j4 = 0; j4 < 8; j4++) {
            float4 wv = *(const float4*)&w_k[d * D_ + h * 32 + j4 * 4];
            #pragma unroll
            for (int m = 0; m < 4; m++) {
                float4 qv = *(const float4*)&qh[(g * 4 + m) * D_ + h * 32 + j4 * 4];
                acc[m] += wv.x * qv.x + wv.y * qv.y + wv.z * qv.z + wv.w * qv.w;
            }
        }
        #pragma unroll
        for (int m = 0; m < 4; m++) rs[((g * 4 + m) * 4 + h) * D_ + d] = acc[m];
    }
    __syncthreads();   // rs ready; em/qm dead -> sc alias safe

    // ---- phase C: scores (warp-autonomous, batch = b0 + w) ----
    const int w = t >> 5, lane = t & 31;
    const int rg = lane >> 3, u = lane & 7;
    const __half* epg = g_ep16 + (size_t)(b0 + w) * (S_ * D_);
    const float scale = 0.17677669529663689f;  // 1/sqrt(32)

    #pragma unroll 4
    for (int iter = 0; iter < 16; iter++) {
        const int s = iter * 4 + rg;
        const __half* ebase = epg + s * D_ + u * 4;
        float acc[4] = {0.f, 0.f, 0.f, 0.f};
        #pragma unroll
        for (int k = 0; k < 4; k++) {
            uint2 uu = *(const uint2*)(ebase + 32 * k);
            __half2* hp = (__half2*)&uu;
            float2 f0 = __half22float2(hp[0]);
            float2 f1 = __half22float2(hp[1]);
            #pragma unroll
            for (int h = 0; h < 4; h++) {
                float4 rv = *(const float4*)&rs[(w * 4 + h) * D_ + u * 4 + 32 * k];
                acc[h] += f0.x * rv.x + f0.y * rv.y + f1.x * rv.z + f1.y * rv.w;
            }
        }
        #pragma unroll
        for (int o = 1; o < 8; o <<= 1) {
            #pragma unroll
            for (int h = 0; h < 4; h++)
                acc[h] += __shfl_xor_sync(0xffffffffu, acc[h], o);
        }
        if (u == 0) {
            #pragma unroll
            for (int h = 0; h < 4; h++)
                sc[w * 256 + h * 64 + s] = acc[h] * scale;
        }
    }
    __syncwarp();

    // ---- phase D: softmax (warp-local), write probs ----
    #pragma unroll
    for (int h = 0; h < 4; h++) {
        float v0 = sc[w * 256 + h * 64 + lane];
        float v1 = sc[w * 256 + h * 64 + 32 + lane];
        float mx = fmaxf(v0, v1);
        #pragma unroll
        for (int o = 16; o > 0; o >>= 1) mx = fmaxf(mx, __shfl_xor_sync(0xffffffffu, mx, o));
        float e0 = expf(v0 - mx), e1 = expf(v1 - mx);
        float sum = e0 + e1;
        #pragma unroll
        for (int o = 16; o > 0; o >>= 1) sum += __shfl_xor_sync(0xffffffffu, sum, o);
        float inv = 1.0f / sum;
        float* po = g_probs + ((size_t)(b0 + w) * H_ + h) * S_;
        po[lane] = e0 * inv;
        po[32 + lane] = e1 * inv;
    }
}

// ---------------------------------------------------------------------------
// Fused attention + MLP.  Block bi owns sources 8bi..8bi+7;
// consumers b = 2bi+q + 1024k (q=0..1, k=0..3), all heads.
// Attn: warp w = (q = w>>2, h = w&3) OWNS tile j = 8bi+4q+h (read exactly once).
// Lane: u = lane&15 -> dims 8u..8u+7 (uint4 loads), z = lane>>4 -> s parity.
// Full-s accumulators for 4 consumers; one shfl_xor(16) round merges parities.
__global__ void __launch_bounds__(256) kAttnMLP(
    const float* __restrict__ w3a, const float* __restrict__ b3a,
    const float* __restrict__ g3a, const float* __restrict__ be3a,
    const float* __restrict__ w3b, const float* __restrict__ b3b,
    const float* __restrict__ g3b, const float* __restrict__ be3b,
    float* __restrict__ out)
{
    __shared__ float pr[2048];                    // 8 KB  pr[q*1024 + k*256 + h*64 + s]
    __shared__ __align__(16) float as[8 * 512];   // 16 KB attn rows [q*4+k][512]
    __shared__ __align__(16) float h1[8 * D_];    // 4 KB

    const int t = threadIdx.x, bi = blockIdx.x;

    // stage probs for 8 consumers x 4 heads
    for (int z = t; z < 2048; z += 256) {
        int q = z >> 10, k = (z >> 8) & 3, hs = z & 255;   // hs = h*64 + s
        int b = 2 * bi + q + 1024 * k;
        pr[z] = g_probs[(size_t)b * (H_ * S_) + hs];
    }
    __syncthreads();

    // ---- attention: warp-per-tile, barrier-free ----
    {
        const int w = t >> 5, lane = t & 31;
        const int q = w >> 2, h = w & 3;
        const int u = lane & 15, z = lane >> 4;
        const int j = 8 * bi + 4 * q + h;
        const __half* epg = g_ep16 + (size_t)j * (S_ * D_) + 8 * u;
        const float* prb = &pr[q * 1024 + h * 64];   // + k*256 + s

        float acc[32];   // [k][0..7] for dims 8u..8u+7
        #pragma unroll
        for (int i = 0; i < 32; i++) acc[i] = 0.f;

        #pragma unroll 4
        for (int it = 0; it < 32; it++) {
            const int s = 2 * it + z;
            uint4 uu = *(const uint4*)(epg + s * D_);
            __half2* hp2 = (__half2*)&uu;
            float e[8];
            #pragma unroll
            for (int i = 0; i < 4; i++) {
                float2 f = __half22float2(hp2[i]);
                e[2 * i] = f.x;
                e[2 * i + 1] = f.y;
            }
            #pragma unroll
            for (int k = 0; k < 4; k++) {
                float p = prb[k * 256 + s];   // 2-way LDS broadcast
                #pragma unroll
                for (int i = 0; i < 8; i++) acc[k * 8 + i] += p * e[i];
            }
        }
        // merge s-parity halves (lane <-> lane^16)
        #pragma unroll
        for (int i = 0; i < 32; i++)
            acc[i] += __shfl_xor_sync(0xffffffffu, acc[i], 16);

        if (z == 0) {
            #pragma unroll
            for (int k = 0; k < 4; k++) {
                float* dst = &as[(q * 4 + k) * 512 + h * D_ + 8 * u];
                *(float4*)dst       = make_float4(acc[k*8+0], acc[k*8+1], acc[k*8+2], acc[k*8+3]);
                *(float4*)(dst + 4) = make_float4(acc[k*8+4], acc[k*8+5], acc[k*8+6], acc[k*8+7]);
            }
        }
    }
    __syncthreads();

    // ---- MLP: 8 rows of as -> out. g = t>>7 owns rows g*4+m. ----
    const int d = t & 127, g = t >> 7;
    float acc[4];
    #pragma unroll
    for (int m = 0; m < 4; m++) acc[m] = 0.f;
    for (int i0 = 0; i0 < 512; i0 += 4) {
        float wv0 = w3a[(i0 + 0) * D_ + d];
        float wv1 = w3a[(i0 + 1) * D_ + d];
        float wv2 = w3a[(i0 + 2) * D_ + d];
        float wv3 = w3a[(i0 + 3) * D_ + d];
        #pragma unroll
        for (int m = 0; m < 4; m++) {
            float4 av = *(const float4*)&as[(g * 4 + m) * 512 + i0];  // broadcast
            acc[m] += av.x * wv0 + av.y * wv1 + av.z * wv2 + av.w * wv3;
        }
    }
    {
        float bb = b3a[d], gg = g3a[d], be = be3a[d];
        #pragma unroll
        for (int m = 0; m < 4; m++) {
            float v = (acc[m] + bb) * gg + be;
            h1[(g * 4 + m) * D_ + d] = fmaxf(v, 0.f);
        }
    }
    __syncthreads();

    #pragma unroll
    for (int m = 0; m < 4; m++) acc[m] = 0.f;
    for (int i0 = 0; i0 < D_; i0 += 4) {
        float wv0 = w3b[(i0 + 0) * D_ + d];
        float wv1 = w3b[(i0 + 1) * D_ + d];
        float wv2 = w3b[(i0 + 2) * D_ + d];
        float wv3 = w3b[(i0 + 3) * D_ + d];
        #pragma unroll
        for (int m = 0; m < 4; m++) {
            float4 hv = *(const float4*)&h1[(g * 4 + m) * D_ + i0];
            acc[m] += hv.x * wv0 + hv.y * wv1 + hv.z * wv2 + hv.w * wv3;
        }
    }
    {
        float bb = b3b[d], gg = g3b[d], be = be3b[d];
        #pragma unroll
        for (int m = 0; m < 4; m++) {
            float v = (acc[m] + bb) * gg + be;
            int b_out = 2 * bi + g + 1024 * m;
            out[(size_t)b_out * D_ + d] = fmaxf(v, 0.f);
        }
    }
}

// ---------------------------------------------------------------------------
extern "C" void kernel_launch(void* const* d_in, const int* in_sizes, int n_in,
                              void* d_out, int out_size) {
    const float* x    = (const float*)d_in[0];
    const float* w_q  = (const float*)d_in[1];
    const float* b_q  = (const float*)d_in[2];
    const float* w_k  = (const float*)d_in[3];
    // d_in[4] = b_k: constant over s -> cancels in softmax. Unused.
    const float* w2   = (const float*)d_in[5];
    const float* b2   = (const float*)d_in[6];
    const float* w3a  = (const float*)d_in[7];
    const float* b3a  = (const float*)d_in[8];
    const float* g3a  = (const float*)d_in[9];
    const float* be3a = (const float*)d_in[10];
    const float* w3b  = (const float*)d_in[11];
    const float* b3b  = (const float*)d_in[12];
    const float* g3b  = (const float*)d_in[13];
    const float* be3b = (const float*)d_in[14];
    float* out = (float*)d_out;

    kPre     <<<B_ / 8, 256>>>(x, w_q, b_q, w2, b2, w_k);
    kAttnMLP <<<B_ / 8, 256>>>(w3a, b3a, g3a, be3a, w3b, b3b, g3b, be3b, out);
}